// round 3
// baseline (speedup 1.0000x reference)
#include <cuda_runtime.h>
#include <math.h>

#define BSZ 32
#define QN  600
#define NC  152
#define TT  32
#define NT  1024          // BSZ*TT
#define NR  19200         // BSZ*QN
#define ROWS 16           // rows per cost block (one warp per row)
#define THREADS 512
#define NWARP 16
#define TSTRIDE 601       // odd stride -> conflict-free tile rows
#define NCOSTX 1200       // NR/ROWS

struct CostSmem {
    float s_cx[NT], s_cy[NT], s_w[NT], s_h[NT];
    float s_x0[NT], s_y0[NT], s_x1[NT], s_y1[NT];
    int   s_id[NT];
    float s_prob[ROWS][NC];
};

struct MatchSmem {
    double u[34];
    double redv[2][NWARP];
    int    redi[2][NWARP];
    int    way[QN];
    int    p[QN];
    float  t_cx[TT], t_cy[TT], t_w[TT], t_h[TT];
    float  t_x0[TT], t_y0[TT], t_x1[TT], t_y1[TT];
    int    t_id[TT];
    float  tile[TT * TSTRIDE];   // tile[t*TSTRIDE + q]
};

// ---------------------------------------------------------------------------
// GIoU + L1 + class cost for one (pred, target) pair
// ---------------------------------------------------------------------------
__device__ __forceinline__ float pair_cost(
    float ocx, float ocy, float ow, float oh,
    float ox0, float oy0, float ox1, float oy1, float oarea,
    float tcx, float tcy, float tw, float th,
    float tx0, float ty0, float tx1, float ty1, float prob)
{
    float l1 = fabsf(ocx - tcx) + fabsf(ocy - tcy) + fabsf(ow - tw) + fabsf(oh - th);
    float ta  = (tx1 - tx0) * (ty1 - ty0);
    float ltx = fmaxf(ox0, tx0), lty = fmaxf(oy0, ty0);
    float rbx = fminf(ox1, tx1), rby = fminf(oy1, ty1);
    float iw  = fmaxf(rbx - ltx, 0.f), ih = fmaxf(rby - lty, 0.f);
    float inter = iw * ih;
    float uni   = oarea + ta - inter;
    float cx0 = fminf(ox0, tx0), cy0 = fminf(oy0, ty0);
    float cx1 = fmaxf(ox1, tx1), cy1 = fmaxf(oy1, ty1);
    float cw  = fmaxf(cx1 - cx0, 0.f), ch = fmaxf(cy1 - cy0, 0.f);
    float ac  = cw * ch;
    float iou  = __fdividef(inter, uni);
    float giou = iou - __fdividef(ac - uni, ac);
    return l1 - prob - giou;
}

// ---------------------------------------------------------------------------
// Cost part: full C[bs*Q, bs*T] (one warp per prediction row)
// ---------------------------------------------------------------------------
__device__ void run_cost(
    CostSmem* sm, int xb, int which,
    const float* __restrict__ logits, const float* __restrict__ boxes,
    const float* __restrict__ tbbox,  const int* __restrict__ tids,
    float* __restrict__ out)
{
    float* __restrict__ C = out + (size_t)which * ((size_t)NR * NT);
    const int tid = threadIdx.x;

    for (int j = tid; j < NT; j += THREADS) {
        float cx = tbbox[j*4+0], cy = tbbox[j*4+1];
        float w  = tbbox[j*4+2], h  = tbbox[j*4+3];
        sm->s_cx[j] = cx; sm->s_cy[j] = cy; sm->s_w[j] = w; sm->s_h[j] = h;
        sm->s_x0[j] = cx - 0.5f*w; sm->s_y0[j] = cy - 0.5f*h;
        sm->s_x1[j] = cx + 0.5f*w; sm->s_y1[j] = cy + 0.5f*h;
        sm->s_id[j] = tids[j];
    }

    const int warp = tid >> 5, lane = tid & 31;
    const int row  = xb * ROWS + warp;
    const float* lrow = logits + (size_t)row * NC;

    float m = -1e30f;
    for (int k = lane; k < NC; k += 32) m = fmaxf(m, lrow[k]);
    #pragma unroll
    for (int o = 16; o; o >>= 1) m = fmaxf(m, __shfl_xor_sync(~0u, m, o));
    float s = 0.f;
    for (int k = lane; k < NC; k += 32) {
        float e = __expf(lrow[k] - m);
        sm->s_prob[warp][k] = e;
        s += e;
    }
    #pragma unroll
    for (int o = 16; o; o >>= 1) s += __shfl_xor_sync(~0u, s, o);
    const float inv = __fdividef(1.f, s);
    for (int k = lane; k < NC; k += 32) sm->s_prob[warp][k] *= inv;
    __syncthreads();

    const float ocx = boxes[row*4+0], ocy = boxes[row*4+1];
    const float ow  = boxes[row*4+2], oh  = boxes[row*4+3];
    const float ox0 = ocx - 0.5f*ow, oy0 = ocy - 0.5f*oh;
    const float ox1 = ocx + 0.5f*ow, oy1 = ocy + 0.5f*oh;
    const float oarea = (ox1 - ox0) * (oy1 - oy0);

    float* __restrict__ orow = C + (size_t)row * NT;
    const float* pr = sm->s_prob[warp];

    for (int j = lane; j < NT; j += 32) {
        orow[j] = pair_cost(ocx, ocy, ow, oh, ox0, oy0, ox1, oy1, oarea,
                            sm->s_cx[j], sm->s_cy[j], sm->s_w[j], sm->s_h[j],
                            sm->s_x0[j], sm->s_y0[j], sm->s_x1[j], sm->s_y1[j],
                            pr[sm->s_id[j]]);
    }
}

// ---------------------------------------------------------------------------
// Match part: build own 32x600 diagonal tile, run offset-folded JV.
// ---------------------------------------------------------------------------
__device__ void run_match(
    MatchSmem* sm, int b, int which,
    const float* __restrict__ logits, const float* __restrict__ boxes,
    const float* __restrict__ tbbox,  const int* __restrict__ tids,
    float* __restrict__ out)
{
    const int tid  = threadIdx.x;
    const int warp = tid >> 5, lane = tid & 31;

    if (tid < TT) {
        int j = b * TT + tid;
        float cx = tbbox[j*4+0], cy = tbbox[j*4+1];
        float w  = tbbox[j*4+2], h  = tbbox[j*4+3];
        sm->t_cx[tid] = cx; sm->t_cy[tid] = cy; sm->t_w[tid] = w; sm->t_h[tid] = h;
        sm->t_x0[tid] = cx - 0.5f*w; sm->t_y0[tid] = cy - 0.5f*h;
        sm->t_x1[tid] = cx + 0.5f*w; sm->t_y1[tid] = cy + 0.5f*h;
        sm->t_id[tid] = tids[j];
    }
    for (int j = tid; j < QN; j += THREADS) sm->p[j] = 0;
    if (tid < 34) sm->u[tid] = 0.0;
    __syncthreads();

    // ---- build tile[t][q]: one warp per prediction row q ----
    for (int mq = 0; ; mq++) {
        int q = warp + NWARP * mq;
        if (q >= QN) break;
        const float* lrow = logits + (size_t)(b * QN + q) * NC;
        float r[5], mx = -1e30f;
        #pragma unroll
        for (int jj = 0; jj < 5; jj++) {
            int k = lane + 32 * jj;
            r[jj] = (k < NC) ? lrow[k] : -1e30f;
            mx = fmaxf(mx, r[jj]);
        }
        #pragma unroll
        for (int o = 16; o; o >>= 1) mx = fmaxf(mx, __shfl_xor_sync(~0u, mx, o));
        float ss = 0.f;
        #pragma unroll
        for (int jj = 0; jj < 5; jj++) {
            int k = lane + 32 * jj;
            if (k < NC) ss += __expf(r[jj] - mx);
        }
        #pragma unroll
        for (int o = 16; o; o >>= 1) ss += __shfl_xor_sync(~0u, ss, o);
        const float inv = __fdividef(1.f, ss);

        const float4 pb = *reinterpret_cast<const float4*>(boxes + (size_t)(b*QN + q)*4);
        const float ocx = pb.x, ocy = pb.y, ow = pb.z, oh = pb.w;
        const float ox0 = ocx - 0.5f*ow, oy0 = ocy - 0.5f*oh;
        const float ox1 = ocx + 0.5f*ow, oy1 = ocy + 0.5f*oh;
        const float oarea = (ox1 - ox0) * (oy1 - oy0);

        const int t = lane;                 // one target per lane
        const float prob = __expf(lrow[sm->t_id[t]] - mx) * inv;
        sm->tile[t * TSTRIDE + q] = pair_cost(
            ocx, ocy, ow, oh, ox0, oy0, ox1, oy1, oarea,
            sm->t_cx[t], sm->t_cy[t], sm->t_w[t], sm->t_h[t],
            sm->t_x0[t], sm->t_y0[t], sm->t_x1[t], sm->t_y1[t], prob);
    }
    __syncthreads();

    // ---- JV with offset-folded potentials ----
    const int c0 = tid, c1 = tid + THREADS;     // c1 valid only for tid < QN-THREADS
    const int v1ok = (c1 < QN);
    double v0 = 0.0, v1 = 0.0;
    int par = 0;

    for (int i = 1; i <= TT; i++) {
        double s0 = 1e18, s1 = 1e18;
        int used0 = 0, used1 = v1ok ? 0 : 1;
        int j0 = -1, i0 = i, jf;
        double off = 0.0;

        for (;;) {
            if (j0 == c0) used0 = 1;
            if (j0 == c1) used1 = 1;
            const double ui0p = sm->u[i0] - off;
            const float* crow = sm->tile + (i0 - 1) * TSTRIDE;

            double lmin = 1e18; int lidx = 1 << 30;
            if (!used0) {
                double cur = (double)crow[c0] - ui0p - v0;
                if (cur < s0) { s0 = cur; sm->way[c0] = j0; }
                if (s0 < lmin) { lmin = s0; lidx = c0; }
            }
            if (!used1) {
                double cur = (double)crow[c1] - ui0p - v1;
                if (cur < s1) { s1 = cur; sm->way[c1] = j0; }
                if (s1 < lmin) { lmin = s1; lidx = c1; }
            }
            #pragma unroll
            for (int o = 16; o; o >>= 1) {
                double om = __shfl_xor_sync(~0u, lmin, o);
                int    oi = __shfl_xor_sync(~0u, lidx, o);
                if (om < lmin || (om == lmin && oi < lidx)) { lmin = om; lidx = oi; }
            }
            if (lane == 0) { sm->redv[par][warp] = lmin; sm->redi[par][warp] = lidx; }
            __syncthreads();
            double bm = sm->redv[par][0]; int bj = sm->redi[par][0];
            #pragma unroll
            for (int w = 1; w < NWARP; w++) {
                double wv = sm->redv[par][w]; int wi = sm->redi[par][w];
                if (wv < bm || (wv == bm && wi < bj)) { bm = wv; bj = wi; }
            }
            par ^= 1;
            off = bm;                       // off accumulates deltas (== current smin)
            const int prj = sm->p[bj];
            if (prj == 0) { jf = bj; break; }
            i0 = prj; j0 = bj;
        }

        // deferred potential updates (p still pre-augmentation)
        if (used0) {
            double dv = off - s0;           // s frozen at selection time
            v0 -= dv;
            sm->u[sm->p[c0]] += dv;         // distinct rows -> no race
        }
        if (v1ok && used1) {
            double dv = off - s1;
            v1 -= dv;
            sm->u[sm->p[c1]] += dv;
        }
        __syncthreads();
        if (tid == 0) {
            sm->u[i] += off;                // virtual start column
            int j = jf;
            for (;;) {
                int jp = sm->way[j];
                sm->p[j] = (jp < 0) ? i : sm->p[jp];
                if (jp < 0) break;
                j = jp;
            }
        }
        __syncthreads();
    }

    if (tid == 0) {
        float* op = out + (size_t)2 * NR * NT + (size_t)which * 2 * NT; // ps / po
        float* ot = op + NT;                                            // ts / to
        int k = 0;
        for (int q = 0; q < QN; q++) {
            if (sm->p[q]) {
                op[b * TT + k] = (float)q;
                ot[b * TT + k] = (float)(sm->p[q] - 1);
                k++;
            }
        }
    }
}

// ---------------------------------------------------------------------------
// Fused kernel: blocks [0,64) = match (scheduled first), rest = cost.
// ---------------------------------------------------------------------------
__global__ __launch_bounds__(THREADS, 2) void fused_kernel(
    const float* __restrict__ lg0, const float* __restrict__ lg1,
    const float* __restrict__ bx0, const float* __restrict__ bx1,
    const float* __restrict__ tb0, const float* __restrict__ tb1,
    const int*   __restrict__ id0, const int*   __restrict__ id1,
    float* __restrict__ out)
{
    extern __shared__ unsigned char smem_raw[];
    const int bi = blockIdx.x;

    if (bi < 64) {
        const int b = bi & 31, which = bi >> 5;
        run_match(reinterpret_cast<MatchSmem*>(smem_raw), b, which,
                  which ? lg1 : lg0, which ? bx1 : bx0,
                  which ? tb1 : tb0, which ? id1 : id0, out);
    } else {
        const int cb = bi - 64;
        const int which = cb / NCOSTX, xb = cb % NCOSTX;
        run_cost(reinterpret_cast<CostSmem*>(smem_raw), xb, which,
                 which ? lg1 : lg0, which ? bx1 : bx0,
                 which ? tb1 : tb0, which ? id1 : id0, out);
    }
}

// ---------------------------------------------------------------------------
extern "C" void kernel_launch(void* const* d_in, const int* in_sizes, int n_in,
                              void* d_out, int out_size) {
    const float* lg0 = (const float*)d_in[0];
    const float* lg1 = (const float*)d_in[1];
    const float* bx0 = (const float*)d_in[2];
    const float* bx1 = (const float*)d_in[3];
    const float* tb0 = (const float*)d_in[4];
    const float* tb1 = (const float*)d_in[5];
    const int*   id0 = (const int*)d_in[6];
    const int*   id1 = (const int*)d_in[7];
    float* out = (float*)d_out;

    size_t smem = sizeof(MatchSmem) > sizeof(CostSmem)
                ? sizeof(MatchSmem) : sizeof(CostSmem);
    cudaFuncSetAttribute(fused_kernel,
                         cudaFuncAttributeMaxDynamicSharedMemorySize, (int)smem);

    fused_kernel<<<64 + 2 * NCOSTX, THREADS, smem>>>(
        lg0, lg1, bx0, bx1, tb0, tb1, id0, id1, out);
}

// round 4
// speedup vs baseline: 3.2816x; 3.2816x over previous
#include <cuda_runtime.h>
#include <math.h>

#define BSZ 32
#define QN  600
#define NC  152
#define TT  32
#define NT  1024          // BSZ*TT
#define NR  19200         // BSZ*QN
#define TSTRIDE 601       // odd stride -> conflict-free tile rows

// ===========================================================================
// Kernel 1: cost matrices. 256 threads, 8 warps x 4 rows = 32 rows per block.
// Targets staged as float4 + precomputed area; ~3 LDS per output element.
// ===========================================================================
#define CTH 256
#define RPW 4             // rows per warp

struct CostSmem {
    float4 s_box[NT];     // cxcywh
    float4 s_xy[NT];      // xyxy
    float  s_ta[NT];      // target area
    int    s_id[NT];
    float  s_prob[32][NC];
};

__global__ __launch_bounds__(CTH, 3) void cost_kernel(
    const float* __restrict__ lg0, const float* __restrict__ lg1,
    const float* __restrict__ bx0, const float* __restrict__ bx1,
    const float* __restrict__ tb0, const float* __restrict__ tb1,
    const int*   __restrict__ id0, const int*   __restrict__ id1,
    float* __restrict__ out)
{
    __shared__ CostSmem sm;
    const int which = blockIdx.z;
    const float* __restrict__ logits = which ? lg1 : lg0;
    const float* __restrict__ boxes  = which ? bx1 : bx0;
    const float* __restrict__ tbbox  = which ? tb1 : tb0;
    const int*   __restrict__ tids   = which ? id1 : id0;
    float* __restrict__ C = out + (size_t)which * ((size_t)NR * NT);

    const int tid = threadIdx.x;
    for (int j = tid; j < NT; j += CTH) {
        float4 t = *reinterpret_cast<const float4*>(tbbox + (size_t)j * 4);
        sm.s_box[j] = t;
        float x0 = t.x - 0.5f*t.z, y0 = t.y - 0.5f*t.w;
        float x1 = t.x + 0.5f*t.z, y1 = t.y + 0.5f*t.w;
        sm.s_xy[j] = make_float4(x0, y0, x1, y1);
        sm.s_ta[j] = (x1 - x0) * (y1 - y0);
        sm.s_id[j] = tids[j];
    }

    const int warp = tid >> 5, lane = tid & 31;
    const int row0 = blockIdx.x * 32 + warp * RPW;

    float ocx[RPW], ocy[RPW], ow[RPW], oh[RPW];
    float ox0[RPW], oy0[RPW], ox1[RPW], oy1[RPW], oarea[RPW];

    #pragma unroll
    for (int rr = 0; rr < RPW; rr++) {
        const int row = row0 + rr;
        const float* lrow = logits + (size_t)row * NC;
        // warp softmax, single exp pass
        float r[5], m = -1e30f;
        #pragma unroll
        for (int jj = 0; jj < 5; jj++) {
            int k = lane + 32 * jj;
            r[jj] = (k < NC) ? lrow[k] : -1e30f;
            m = fmaxf(m, r[jj]);
        }
        #pragma unroll
        for (int o = 16; o; o >>= 1) m = fmaxf(m, __shfl_xor_sync(~0u, m, o));
        float s = 0.f;
        #pragma unroll
        for (int jj = 0; jj < 5; jj++) {
            int k = lane + 32 * jj;
            if (k < NC) { r[jj] = __expf(r[jj] - m); s += r[jj]; }
        }
        #pragma unroll
        for (int o = 16; o; o >>= 1) s += __shfl_xor_sync(~0u, s, o);
        const float inv = __fdividef(1.f, s);
        #pragma unroll
        for (int jj = 0; jj < 5; jj++) {
            int k = lane + 32 * jj;
            if (k < NC) sm.s_prob[warp*RPW + rr][k] = r[jj] * inv;
        }
        const float4 pb = *reinterpret_cast<const float4*>(boxes + (size_t)row * 4);
        ocx[rr] = pb.x; ocy[rr] = pb.y; ow[rr] = pb.z; oh[rr] = pb.w;
        ox0[rr] = pb.x - 0.5f*pb.z; oy0[rr] = pb.y - 0.5f*pb.w;
        ox1[rr] = pb.x + 0.5f*pb.z; oy1[rr] = pb.y + 0.5f*pb.w;
        oarea[rr] = (ox1[rr] - ox0[rr]) * (oy1[rr] - oy0[rr]);
    }
    __syncthreads();

    for (int j = lane; j < NT; j += 32) {
        const float4 tb  = sm.s_box[j];
        const float4 txy = sm.s_xy[j];
        const float  ta  = sm.s_ta[j];
        const int    id  = sm.s_id[j];
        #pragma unroll
        for (int rr = 0; rr < RPW; rr++) {
            float prob = sm.s_prob[warp*RPW + rr][id];
            float l1 = fabsf(ocx[rr]-tb.x) + fabsf(ocy[rr]-tb.y)
                     + fabsf(ow[rr]-tb.z)  + fabsf(oh[rr]-tb.w);
            float ltx = fmaxf(ox0[rr], txy.x), lty = fmaxf(oy0[rr], txy.y);
            float rbx = fminf(ox1[rr], txy.z), rby = fminf(oy1[rr], txy.w);
            float iw  = fmaxf(rbx - ltx, 0.f), ih = fmaxf(rby - lty, 0.f);
            float inter = iw * ih;
            float uni   = oarea[rr] + ta - inter;
            float cx0 = fminf(ox0[rr], txy.x), cy0 = fminf(oy0[rr], txy.y);
            float cx1 = fmaxf(ox1[rr], txy.z), cy1 = fmaxf(oy1[rr], txy.w);
            float cw  = fmaxf(cx1 - cx0, 0.f), ch = fmaxf(cy1 - cy0, 0.f);
            float ac  = cw * ch;
            float iou  = __fdividef(inter, uni);
            float giou = iou - __fdividef(ac - uni, ac);
            C[(size_t)(row0 + rr) * NT + j] = l1 - prob - giou;
        }
    }
}

// ===========================================================================
// Kernel 2: exact JV, fp32, offset-folded potentials, registers + REDUX.
// 256 threads, 64 blocks (one per problem), one barrier per inner iteration.
// ===========================================================================
#define MTH 256
#define NW  8
#define KS  3             // column slots per thread (3*256 >= 600)

struct MatchSmem {
    float              u[34];
    unsigned long long red[2][NW];
    int                way[QN];
    int                p[QN];
    float              tile[TT * TSTRIDE];
};

__device__ __forceinline__ unsigned fmap(float f) {
    unsigned b = __float_as_uint(f);
    return b ^ (unsigned)(((int)b >> 31) | 0x80000000);
}
__device__ __forceinline__ float funmap(unsigned m) {
    unsigned b = (m & 0x80000000u) ? (m ^ 0x80000000u) : ~m;
    return __uint_as_float(b);
}

__global__ __launch_bounds__(MTH, 1) void match_kernel(
    const float* __restrict__ Cfull, float* __restrict__ outbase)
{
    extern __shared__ unsigned char smem_raw[];
    MatchSmem* sm = reinterpret_cast<MatchSmem*>(smem_raw);

    const int b     = blockIdx.x & 31;
    const int which = blockIdx.x >> 5;
    const float* __restrict__ C = Cfull + (size_t)which * ((size_t)NR * NT);
    const int tid  = threadIdx.x;
    const int warp = tid >> 5;

    // stage diagonal block: tile[t*TSTRIDE + q] = C[b, q, b*T + t]
    for (int idx = tid; idx < TT * QN; idx += MTH) {
        int q = idx >> 5, t = idx & 31;                 // coalesced 128B reads
        sm->tile[t * TSTRIDE + q] = C[((size_t)(b * QN + q)) * NT + b * TT + t];
    }
    for (int j = tid; j < QN; j += MTH) sm->p[j] = 0;
    if (tid < 34) sm->u[tid] = 0.f;
    __syncthreads();

    const int c_[KS] = { tid, tid + MTH, tid + 2 * MTH };
    float v_[KS] = {0.f, 0.f, 0.f};
    int par = 0;

    for (int i = 1; i <= TT; i++) {
        float s_[KS] = {1e30f, 1e30f, 1e30f};
        int usedm = (c_[2] < QN) ? 0 : 4;               // mark invalid slot used
        int j0 = -1, i0 = i, jf;
        float off = 0.f;

        for (;;) {
            #pragma unroll
            for (int k = 0; k < KS; k++)
                if (j0 == c_[k]) usedm |= 1 << k;

            const float ui0p = sm->u[i0] - off;
            const float* crow = sm->tile + (i0 - 1) * TSTRIDE;

            float lmin = 1e30f; int lidx = 0x7fffffff;
            #pragma unroll
            for (int k = 0; k < KS; k++) {
                if (!((usedm >> k) & 1)) {
                    float cur = crow[c_[k]] - ui0p - v_[k];
                    if (cur < s_[k]) { s_[k] = cur; sm->way[c_[k]] = j0; }
                    if (s_[k] < lmin) { lmin = s_[k]; lidx = c_[k]; }
                }
            }
            // warp argmin: hw redux on monotone u32, then redux on tie indices
            unsigned mu   = fmap(lmin);
            unsigned wmin = __reduce_min_sync(~0u, mu);
            unsigned cand = (mu == wmin) ? (unsigned)lidx : 0xffffffffu;
            unsigned widx = __reduce_min_sync(~0u, cand);
            if ((tid & 31) == 0)
                sm->red[par][warp] = ((unsigned long long)wmin << 32) | widx;
            __syncthreads();
            unsigned long long bp = sm->red[par][0];
            #pragma unroll
            for (int w = 1; w < NW; w++) bp = min(bp, sm->red[par][w]);
            par ^= 1;
            off = funmap((unsigned)(bp >> 32));
            const int bj = (int)(unsigned)bp;
            const int prj = sm->p[bj];
            if (prj == 0) { jf = bj; break; }
            i0 = prj; j0 = bj;
        }

        // deferred potential updates (p still pre-augmentation; rows distinct)
        #pragma unroll
        for (int k = 0; k < KS; k++) {
            if (((usedm >> k) & 1) && c_[k] < QN) {
                float dv = off - s_[k];
                v_[k] -= dv;
                sm->u[sm->p[c_[k]]] += dv;
            }
        }
        __syncthreads();
        if (tid == 0) {
            sm->u[i] += off;
            int j = jf;
            for (;;) {
                int jp = sm->way[j];
                sm->p[j] = (jp < 0) ? i : sm->p[jp];
                if (jp < 0) break;
                j = jp;
            }
        }
        __syncthreads();
    }

    if (tid == 0) {
        float* op = outbase + (size_t)2 * NR * NT + (size_t)which * 2 * NT; // ps/po
        float* ot = op + NT;                                                // ts/to
        int k = 0;
        for (int q = 0; q < QN; q++) {
            if (sm->p[q]) {
                op[b * TT + k] = (float)q;
                ot[b * TT + k] = (float)(sm->p[q] - 1);
                k++;
            }
        }
    }
}

// ===========================================================================
extern "C" void kernel_launch(void* const* d_in, const int* in_sizes, int n_in,
                              void* d_out, int out_size) {
    const float* lg0 = (const float*)d_in[0];
    const float* lg1 = (const float*)d_in[1];
    const float* bx0 = (const float*)d_in[2];
    const float* bx1 = (const float*)d_in[3];
    const float* tb0 = (const float*)d_in[4];
    const float* tb1 = (const float*)d_in[5];
    const int*   id0 = (const int*)d_in[6];
    const int*   id1 = (const int*)d_in[7];
    float* out = (float*)d_out;

    cudaFuncSetAttribute(match_kernel,
                         cudaFuncAttributeMaxDynamicSharedMemorySize,
                         (int)sizeof(MatchSmem));

    dim3 cg(NR / 32, 1, 2);   // 600 x 2 blocks
    cost_kernel<<<cg, CTH>>>(lg0, lg1, bx0, bx1, tb0, tb1, id0, id1, out);
    match_kernel<<<64, MTH, sizeof(MatchSmem)>>>(out, out);
}

// round 5
// speedup vs baseline: 3.5845x; 1.0923x over previous
#include <cuda_runtime.h>
#include <math.h>

#define BSZ 32
#define QN  600
#define NC  152
#define TT  32
#define NT  1024          // BSZ*TT
#define NR  19200         // BSZ*QN
#define TSTRIDE 601       // odd stride -> conflict-free tile rows

// ===========================================================================
// Kernel 1: cost matrices. 256 threads, 8 warps x 4 rows = 32 rows per block.
// smem trimmed to 53.4KB -> occupancy 4.
// ===========================================================================
#define CTH 256
#define RPW 4             // rows per warp

struct CostSmem {
    float4 s_box[NT];     // cxcywh
    float4 s_xy[NT];      // xyxy
    unsigned short s_id[NT];
    float  s_prob[32][NC];
};

__global__ __launch_bounds__(CTH, 4) void cost_kernel(
    const float* __restrict__ lg0, const float* __restrict__ lg1,
    const float* __restrict__ bx0, const float* __restrict__ bx1,
    const float* __restrict__ tb0, const float* __restrict__ tb1,
    const int*   __restrict__ id0, const int*   __restrict__ id1,
    float* __restrict__ out)
{
    __shared__ CostSmem sm;
    const int which = blockIdx.z;
    const float* __restrict__ logits = which ? lg1 : lg0;
    const float* __restrict__ boxes  = which ? bx1 : bx0;
    const float* __restrict__ tbbox  = which ? tb1 : tb0;
    const int*   __restrict__ tids   = which ? id1 : id0;
    float* __restrict__ C = out + (size_t)which * ((size_t)NR * NT);

    const int tid = threadIdx.x;
    for (int j = tid; j < NT; j += CTH) {
        float4 t = *reinterpret_cast<const float4*>(tbbox + (size_t)j * 4);
        sm.s_box[j] = t;
        float x0 = t.x - 0.5f*t.z, y0 = t.y - 0.5f*t.w;
        float x1 = t.x + 0.5f*t.z, y1 = t.y + 0.5f*t.w;
        sm.s_xy[j] = make_float4(x0, y0, x1, y1);
        sm.s_id[j] = (unsigned short)tids[j];
    }

    const int warp = tid >> 5, lane = tid & 31;
    const int row0 = blockIdx.x * 32 + warp * RPW;

    float ocx[RPW], ocy[RPW], ow[RPW], oh[RPW];
    float ox0[RPW], oy0[RPW], ox1[RPW], oy1[RPW], oarea[RPW];

    #pragma unroll
    for (int rr = 0; rr < RPW; rr++) {
        const int row = row0 + rr;
        const float* lrow = logits + (size_t)row * NC;
        float r[5], m = -1e30f;
        #pragma unroll
        for (int jj = 0; jj < 5; jj++) {
            int k = lane + 32 * jj;
            r[jj] = (k < NC) ? lrow[k] : -1e30f;
            m = fmaxf(m, r[jj]);
        }
        #pragma unroll
        for (int o = 16; o; o >>= 1) m = fmaxf(m, __shfl_xor_sync(~0u, m, o));
        float s = 0.f;
        #pragma unroll
        for (int jj = 0; jj < 5; jj++) {
            int k = lane + 32 * jj;
            if (k < NC) { r[jj] = __expf(r[jj] - m); s += r[jj]; }
        }
        #pragma unroll
        for (int o = 16; o; o >>= 1) s += __shfl_xor_sync(~0u, s, o);
        const float inv = __fdividef(1.f, s);
        #pragma unroll
        for (int jj = 0; jj < 5; jj++) {
            int k = lane + 32 * jj;
            if (k < NC) sm.s_prob[warp*RPW + rr][k] = r[jj] * inv;
        }
        const float4 pb = *reinterpret_cast<const float4*>(boxes + (size_t)row * 4);
        ocx[rr] = pb.x; ocy[rr] = pb.y; ow[rr] = pb.z; oh[rr] = pb.w;
        ox0[rr] = pb.x - 0.5f*pb.z; oy0[rr] = pb.y - 0.5f*pb.w;
        ox1[rr] = pb.x + 0.5f*pb.z; oy1[rr] = pb.y + 0.5f*pb.w;
        oarea[rr] = (ox1[rr] - ox0[rr]) * (oy1[rr] - oy0[rr]);
    }
    __syncthreads();

    for (int j = lane; j < NT; j += 32) {
        const float4 tb  = sm.s_box[j];
        const float4 txy = sm.s_xy[j];
        const int    id  = sm.s_id[j];
        const float  ta  = (txy.z - txy.x) * (txy.w - txy.y);
        #pragma unroll
        for (int rr = 0; rr < RPW; rr++) {
            float prob = sm.s_prob[warp*RPW + rr][id];
            float l1 = fabsf(ocx[rr]-tb.x) + fabsf(ocy[rr]-tb.y)
                     + fabsf(ow[rr]-tb.z)  + fabsf(oh[rr]-tb.w);
            float ltx = fmaxf(ox0[rr], txy.x), lty = fmaxf(oy0[rr], txy.y);
            float rbx = fminf(ox1[rr], txy.z), rby = fminf(oy1[rr], txy.w);
            float iw  = fmaxf(rbx - ltx, 0.f), ih = fmaxf(rby - lty, 0.f);
            float inter = iw * ih;
            float uni   = oarea[rr] + ta - inter;
            float cx0 = fminf(ox0[rr], txy.x), cy0 = fminf(oy0[rr], txy.y);
            float cx1 = fmaxf(ox1[rr], txy.z), cy1 = fmaxf(oy1[rr], txy.w);
            float cw  = fmaxf(cx1 - cx0, 0.f), ch = fmaxf(cy1 - cy0, 0.f);
            float ac  = cw * ch;
            float iou  = __fdividef(inter, uni);
            float giou = iou - __fdividef(ac - uni, ac);
            C[(size_t)(row0 + rr) * NT + j] = l1 - prob - giou;
        }
    }
}

// ===========================================================================
// Kernel 2: exact JV with row-reduction + greedy warm start. fp32,
// offset-folded potentials, REDUX argmin, parallel ranked emit.
// ===========================================================================
#define MTH 256
#define NW  8
#define KS  3             // column slots per thread (3*256 >= 600)

struct MatchSmem {
    float              u[34];
    float              rowmin[TT];
    int                rowarg[TT];
    int                unrows[TT];
    int                nun;
    int                cnt;
    int                sq[TT], sr[TT];
    unsigned long long red[2][NW];
    int                way[QN];
    int                p[QN];
    float              tile[TT * TSTRIDE];
};

__device__ __forceinline__ unsigned fmap(float f) {
    unsigned b = __float_as_uint(f);
    return b ^ (unsigned)(((int)b >> 31) | 0x80000000);
}
__device__ __forceinline__ float funmap(unsigned m) {
    unsigned b = (m & 0x80000000u) ? (m ^ 0x80000000u) : ~m;
    return __uint_as_float(b);
}

__global__ __launch_bounds__(MTH, 1) void match_kernel(
    const float* __restrict__ Cfull, float* __restrict__ outbase)
{
    extern __shared__ unsigned char smem_raw[];
    MatchSmem* sm = reinterpret_cast<MatchSmem*>(smem_raw);

    const int b     = blockIdx.x & 31;
    const int which = blockIdx.x >> 5;
    const float* __restrict__ C = Cfull + (size_t)which * ((size_t)NR * NT);
    const int tid  = threadIdx.x;
    const int warp = tid >> 5, lane = tid & 31;

    // stage diagonal block: tile[t*TSTRIDE + q] = C[b, q, b*T + t]
    for (int idx = tid; idx < TT * QN; idx += MTH) {
        int q = idx >> 5, t = idx & 31;                 // coalesced 128B reads
        sm->tile[t * TSTRIDE + q] = C[((size_t)(b * QN + q)) * NT + b * TT + t];
    }
    for (int j = tid; j < QN; j += MTH) sm->p[j] = 0;
    __syncthreads();

    // ---- Phase A: row minima (warp per row, 4 rows per warp) ----
    #pragma unroll
    for (int s = 0; s < 4; s++) {
        const int r = warp + NW * s;
        const float* trow = sm->tile + r * TSTRIDE;
        float lmin = 1e30f; int lidx = 0x7fffffff;
        #pragma unroll
        for (int k = 0; k < 19; k++) {
            int q = lane + 32 * k;
            if (q < QN) {
                float v = trow[q];
                if (v < lmin) { lmin = v; lidx = q; }
            }
        }
        unsigned mu   = fmap(lmin);
        unsigned wmin = __reduce_min_sync(~0u, mu);
        unsigned cand = (mu == wmin) ? (unsigned)lidx : 0xffffffffu;
        unsigned widx = __reduce_min_sync(~0u, cand);
        if (lane == 0) { sm->rowmin[r] = funmap(wmin); sm->rowarg[r] = (int)widx; }
    }
    __syncthreads();

    // ---- Phase B: greedy tight-edge assignment (serial, tiny) ----
    if (tid == 0) {
        int nun = 0;
        for (int i = 1; i <= TT; i++) {
            sm->u[i] = sm->rowmin[i - 1];
            int q = sm->rowarg[i - 1];
            if (sm->p[q] == 0) sm->p[q] = i;
            else sm->unrows[nun++] = i;
        }
        sm->nun = nun;
    }
    __syncthreads();
    const int nun = sm->nun;

    // ---- Phase C: shortest augmenting path for leftover rows ----
    const int c_[KS] = { tid, tid + MTH, tid + 2 * MTH };
    float v_[KS] = {0.f, 0.f, 0.f};
    int par = 0;

    for (int ii = 0; ii < nun; ii++) {
        const int i = sm->unrows[ii];
        float s_[KS] = {1e30f, 1e30f, 1e30f};
        int usedm = (c_[2] < QN) ? 0 : 4;
        int j0 = -1, i0 = i, jf;
        float off = 0.f;

        for (;;) {
            #pragma unroll
            for (int k = 0; k < KS; k++)
                if (j0 == c_[k]) usedm |= 1 << k;

            const float ui0p = sm->u[i0] - off;
            const float* crow = sm->tile + (i0 - 1) * TSTRIDE;

            float lmin = 1e30f; int lidx = 0x7fffffff;
            #pragma unroll
            for (int k = 0; k < KS; k++) {
                if (!((usedm >> k) & 1)) {
                    float cur = crow[c_[k]] - ui0p - v_[k];
                    if (cur < s_[k]) { s_[k] = cur; sm->way[c_[k]] = j0; }
                    if (s_[k] < lmin) { lmin = s_[k]; lidx = c_[k]; }
                }
            }
            unsigned mu   = fmap(lmin);
            unsigned wmin = __reduce_min_sync(~0u, mu);
            unsigned cand = (mu == wmin) ? (unsigned)lidx : 0xffffffffu;
            unsigned widx = __reduce_min_sync(~0u, cand);
            if (lane == 0)
                sm->red[par][warp] = ((unsigned long long)wmin << 32) | widx;
            __syncthreads();
            unsigned long long bp = sm->red[par][0];
            #pragma unroll
            for (int w = 1; w < NW; w++) bp = min(bp, sm->red[par][w]);
            par ^= 1;
            off = funmap((unsigned)(bp >> 32));
            const int bj = (int)(unsigned)bp;
            const int prj = sm->p[bj];
            if (prj == 0) { jf = bj; break; }
            i0 = prj; j0 = bj;
        }

        // deferred potential updates (p still pre-augmentation; rows distinct)
        #pragma unroll
        for (int k = 0; k < KS; k++) {
            if (((usedm >> k) & 1) && c_[k] < QN) {
                float dv = off - s_[k];
                v_[k] -= dv;
                sm->u[sm->p[c_[k]]] += dv;
            }
        }
        __syncthreads();
        if (tid == 0) {
            sm->u[i] += off;
            int j = jf;
            for (;;) {
                int jp = sm->way[j];
                sm->p[j] = (jp < 0) ? i : sm->p[jp];
                if (jp < 0) break;
                j = jp;
            }
        }
        __syncthreads();
    }

    // ---- Emit: compact assigned pairs, rank by column, write ----
    if (tid == 0) sm->cnt = 0;
    __syncthreads();
    #pragma unroll
    for (int k = 0; k < KS; k++) {
        int q = c_[k];
        if (q < QN && sm->p[q]) {
            int t = atomicAdd(&sm->cnt, 1);
            sm->sq[t] = q;
            sm->sr[t] = sm->p[q] - 1;
        }
    }
    __syncthreads();
    if (tid < TT) {
        int q = sm->sq[tid], r = sm->sr[tid];
        int rank = 0;
        #pragma unroll
        for (int o = 0; o < TT; o++)
            rank += (__shfl_sync(~0u, q, o) < q) ? 1 : 0;
        float* op = outbase + (size_t)2 * NR * NT + (size_t)which * 2 * NT; // ps/po
        float* ot = op + NT;                                                // ts/to
        op[b * TT + rank] = (float)q;
        ot[b * TT + rank] = (float)r;
    }
}

// ===========================================================================
extern "C" void kernel_launch(void* const* d_in, const int* in_sizes, int n_in,
                              void* d_out, int out_size) {
    const float* lg0 = (const float*)d_in[0];
    const float* lg1 = (const float*)d_in[1];
    const float* bx0 = (const float*)d_in[2];
    const float* bx1 = (const float*)d_in[3];
    const float* tb0 = (const float*)d_in[4];
    const float* tb1 = (const float*)d_in[5];
    const int*   id0 = (const int*)d_in[6];
    const int*   id1 = (const int*)d_in[7];
    float* out = (float*)d_out;

    cudaFuncSetAttribute(match_kernel,
                         cudaFuncAttributeMaxDynamicSharedMemorySize,
                         (int)sizeof(MatchSmem));

    dim3 cg(NR / 32, 1, 2);   // 600 x 2 blocks
    cost_kernel<<<cg, CTH>>>(lg0, lg1, bx0, bx1, tb0, tb1, id0, id1, out);
    match_kernel<<<64, MTH, sizeof(MatchSmem)>>>(out, out);
}